// round 3
// baseline (speedup 1.0000x reference)
#include <cuda_runtime.h>
#include <math.h>

// Problem constants (fixed per reference setup_inputs)
#define B_   8
#define C_   128
#define N_   4096
#define TINV 10.0f        // 1/TEMP
#define EPSN 1e-12f

#define TM 128            // rows per block tile
#define TN 128            // cols per block tile
#define PITCH 132         // smem pitch (multiple of 4 for float4 alignment)

// Scratch: normalized features, [b][n][c] layout (16 MB)
__device__ float g_vt[(size_t)B_ * N_ * C_];

// ---------------------------------------------------------------------------
// Kernel 0: zero the output scalar (harness poisons d_out)
// ---------------------------------------------------------------------------
__global__ void zero_out_kernel(float* out) { out[0] = 0.0f; }

// ---------------------------------------------------------------------------
// Kernel 1: normalize + transpose.
// features [B][C][N] -> g_vt [B][N][C], each point L2-normalized over C.
// One block handles 32 points of one batch. 256 threads.
// ---------------------------------------------------------------------------
__global__ void normalize_kernel(const float* __restrict__ feat) {
    __shared__ float t[C_][33];     // padded to kill bank conflicts
    __shared__ float invn[32];
    const int b   = blockIdx.y;
    const int n0  = blockIdx.x * 32;
    const int tid = threadIdx.x;

    const float* fb = feat + (size_t)b * C_ * N_;

    // Load [C=128][32] tile, coalesced along n
    for (int idx = tid; idx < C_ * 32; idx += 256) {
        int c = idx >> 5, nl = idx & 31;
        t[c][nl] = fb[(size_t)c * N_ + n0 + nl];
    }
    __syncthreads();

    // Each of 8 warps computes norms for 4 points
    const int w = tid >> 5, lane = tid & 31;
    #pragma unroll
    for (int p = 0; p < 4; p++) {
        int nl = w * 4 + p;
        float v0 = t[lane     ][nl];
        float v1 = t[lane + 32][nl];
        float v2 = t[lane + 64][nl];
        float v3 = t[lane + 96][nl];
        float s = v0 * v0 + v1 * v1 + v2 * v2 + v3 * v3;
        #pragma unroll
        for (int o = 16; o > 0; o >>= 1) s += __shfl_xor_sync(0xffffffffu, s, o);
        if (lane == 0) invn[nl] = 1.0f / fmaxf(sqrtf(s), EPSN);
    }
    __syncthreads();

    // Write normalized, transposed: vt[b][n][c] (coalesced along c)
    float* vb = g_vt + ((size_t)b * N_ + n0) * C_;
    for (int idx = tid; idx < 32 * C_; idx += 256) {
        int nl = idx >> 7, c = idx & 127;
        vb[(size_t)nl * C_ + c] = t[c][nl] * invn[nl];
    }
}

// ---------------------------------------------------------------------------
// Kernel 2: fused S = exp(V.V^T * 10), masked row-reductions, log, and
// global mean accumulation. Block = 128 rows of one batch; loops over all
// 4096 columns in 128-wide tiles. 256 threads, 8x8 micro-tile each.
// Dynamic smem: As[128k][132] + Bs[128k][132]  (~132 KB)
// ---------------------------------------------------------------------------
extern __shared__ float smem[];

__global__ void __launch_bounds__(256, 1)
loss_kernel(const int* __restrict__ labels, float* __restrict__ out) {
    float* As = smem;                    // [k][row], pitch 132
    float* Bs = smem + 128 * PITCH;      // [k][col], pitch 132
    __shared__ int lrow[TM];
    __shared__ int lcolS[TN];
    __shared__ float wsum[8];

    const int b     = blockIdx.y;
    const int rbase = blockIdx.x * TM;
    const int tid   = threadIdx.x;
    const int tx    = tid & 15;
    const int ty    = tid >> 4;

    const float* vb = g_vt + (size_t)b * N_ * C_;
    const int*   lb = labels + b * N_;

    // Load A tile: rows [rbase, rbase+128), all K; store transposed As[k][r]
    for (int idx = tid; idx < TM * C_; idx += 256) {
        int r = idx >> 7, c = idx & 127;
        As[c * PITCH + r] = vb[(size_t)(rbase + r) * C_ + c];
    }
    if (tid < TM) lrow[tid] = lb[rbase + tid];
    __syncthreads();

    int   myrow[8], mylab[8];
    float post[8], tott[8];
    #pragma unroll
    for (int i = 0; i < 8; i++) {
        myrow[i] = rbase + ty * 8 + i;
        mylab[i] = lrow[ty * 8 + i];
        post[i] = 0.0f;
        tott[i] = 0.0f;
    }

    for (int ct = 0; ct < N_ / TN; ct++) {
        const int cbase = ct * TN;
        __syncthreads();   // all threads done reading previous Bs
        for (int idx = tid; idx < TN * C_; idx += 256) {
            int r = idx >> 7, c = idx & 127;
            Bs[c * PITCH + r] = vb[(size_t)(cbase + r) * C_ + c];
        }
        if (tid < TN) lcolS[tid] = lb[cbase + tid];
        __syncthreads();

        float acc[8][8];
        #pragma unroll
        for (int i = 0; i < 8; i++)
            #pragma unroll
            for (int j = 0; j < 8; j++) acc[i][j] = 0.0f;

        #pragma unroll 4
        for (int k = 0; k < C_; k++) {
            float4 a0 = *(const float4*)(As + k * PITCH + ty * 8);
            float4 a1 = *(const float4*)(As + k * PITCH + ty * 8 + 4);
            float4 b0 = *(const float4*)(Bs + k * PITCH + tx * 8);
            float4 b1 = *(const float4*)(Bs + k * PITCH + tx * 8 + 4);
            float av[8] = {a0.x, a0.y, a0.z, a0.w, a1.x, a1.y, a1.z, a1.w};
            float bv[8] = {b0.x, b0.y, b0.z, b0.w, b1.x, b1.y, b1.z, b1.w};
            #pragma unroll
            for (int i = 0; i < 8; i++)
                #pragma unroll
                for (int j = 0; j < 8; j++)
                    acc[i][j] = fmaf(av[i], bv[j], acc[i][j]);
        }

        // Fused epilogue: exp, diagonal removal, label masking
        int gcol[8], clab[8];
        #pragma unroll
        for (int j = 0; j < 8; j++) {
            gcol[j] = cbase + tx * 8 + j;
            clab[j] = lcolS[tx * 8 + j];
        }
        #pragma unroll
        for (int i = 0; i < 8; i++) {
            float p = 0.0f, t2 = 0.0f;
            #pragma unroll
            for (int j = 0; j < 8; j++) {
                float e = __expf(acc[i][j] * TINV);
                e = (myrow[i] == gcol[j]) ? 0.0f : e;   // remove diagonal
                t2 += e;
                p += (mylab[i] == clab[j]) ? e : 0.0f;  // positives
            }
            post[i] += p;
            tott[i] += t2;
        }
    }

    // Cross-thread reduction: each row's partials live in 16 tx-threads.
    __syncthreads();                    // done with As/Bs; reuse for reduction
    float* redp = smem;                 // [128][16]
    float* redt = smem + TM * 16;       // [128][16]
    #pragma unroll
    for (int i = 0; i < 8; i++) {
        redp[(ty * 8 + i) * 16 + tx] = post[i];
        redt[(ty * 8 + i) * 16 + tx] = tott[i];
    }
    __syncthreads();

    float dev = 0.0f;
    if (tid < TM) {
        float p = 0.0f, t2 = 0.0f;
        #pragma unroll
        for (int j = 0; j < 16; j++) {
            p  += redp[tid * 16 + j];
            t2 += redt[tid * 16 + j];
        }
        dev = __logf(t2) - __logf(p);   // -log(pos/(pos+neg))
    }

    // Block-reduce dev and accumulate scaled mean into out
    #pragma unroll
    for (int o = 16; o > 0; o >>= 1) dev += __shfl_xor_sync(0xffffffffu, dev, o);
    if ((tid & 31) == 0) wsum[tid >> 5] = dev;
    __syncthreads();
    if (tid == 0) {
        float s = 0.0f;
        #pragma unroll
        for (int w = 0; w < 8; w++) s += wsum[w];
        atomicAdd(out, s * (1.0f / ((float)B_ * (float)N_)));
    }
}

// ---------------------------------------------------------------------------
// Launch
// ---------------------------------------------------------------------------
extern "C" void kernel_launch(void* const* d_in, const int* in_sizes, int n_in,
                              void* d_out, int out_size) {
    const float* feat   = (const float*)d_in[0];
    const int*   labels = (const int*)d_in[1];
    float*       out    = (float*)d_out;

    zero_out_kernel<<<1, 1>>>(out);

    dim3 gn(N_ / 32, B_);
    normalize_kernel<<<gn, 256>>>(feat);

    const size_t smem_bytes = (size_t)2 * 128 * PITCH * sizeof(float); // 135168
    cudaFuncSetAttribute(loss_kernel,
                         cudaFuncAttributeMaxDynamicSharedMemorySize,
                         (int)smem_bytes);
    dim3 gl(N_ / TM, B_);
    loss_kernel<<<gl, 256, smem_bytes>>>(labels, out);
}

// round 4
// speedup vs baseline: 1.0026x; 1.0026x over previous
#include <cuda_runtime.h>
#include <math.h>

// Problem constants (fixed per reference setup_inputs)
#define B_   8
#define C_   128
#define N_   4096
#define TINV 10.0f        // 1/TEMP
#define EPSN 1e-12f

#define TM 128            // rows per block tile
#define TN 128            // cols per block tile
#define PITCH 132         // smem pitch (multiple of 4 for float4 alignment)

// Scratch: normalized features, [b][n][c] layout (16 MB)
__device__ float g_vt[(size_t)B_ * N_ * C_];

// ---------------------------------------------------------------------------
// Kernel 0: zero the output scalar (harness poisons d_out)
// ---------------------------------------------------------------------------
__global__ void zero_out_kernel(float* out) { out[0] = 0.0f; }

// ---------------------------------------------------------------------------
// Kernel 1: normalize + transpose.
// features [B][C][N] -> g_vt [B][N][C], each point L2-normalized over C.
// One block handles 32 points of one batch. 256 threads.
// ---------------------------------------------------------------------------
__global__ void normalize_kernel(const float* __restrict__ feat) {
    __shared__ float t[C_][33];     // padded to kill bank conflicts
    __shared__ float invn[32];
    const int b   = blockIdx.y;
    const int n0  = blockIdx.x * 32;
    const int tid = threadIdx.x;

    const float* fb = feat + (size_t)b * C_ * N_;

    // Load [C=128][32] tile, coalesced along n
    for (int idx = tid; idx < C_ * 32; idx += 256) {
        int c = idx >> 5, nl = idx & 31;
        t[c][nl] = fb[(size_t)c * N_ + n0 + nl];
    }
    __syncthreads();

    // Each of 8 warps computes norms for 4 points
    const int w = tid >> 5, lane = tid & 31;
    #pragma unroll
    for (int p = 0; p < 4; p++) {
        int nl = w * 4 + p;
        float v0 = t[lane     ][nl];
        float v1 = t[lane + 32][nl];
        float v2 = t[lane + 64][nl];
        float v3 = t[lane + 96][nl];
        float s = v0 * v0 + v1 * v1 + v2 * v2 + v3 * v3;
        #pragma unroll
        for (int o = 16; o > 0; o >>= 1) s += __shfl_xor_sync(0xffffffffu, s, o);
        if (lane == 0) invn[nl] = 1.0f / fmaxf(sqrtf(s), EPSN);
    }
    __syncthreads();

    // Write normalized, transposed: vt[b][n][c] (coalesced along c)
    float* vb = g_vt + ((size_t)b * N_ + n0) * C_;
    for (int idx = tid; idx < 32 * C_; idx += 256) {
        int nl = idx >> 7, c = idx & 127;
        vb[(size_t)nl * C_ + c] = t[c][nl] * invn[nl];
    }
}

// ---------------------------------------------------------------------------
// Kernel 2: fused S = exp(V.V^T * 10), masked row-reductions, log, and
// global mean accumulation. Block = 128 rows of one batch; loops over all
// 4096 columns in 128-wide tiles. 256 threads, 8x8 micro-tile each.
// Dynamic smem: As[128k][132] + Bs[128k][132]  (~132 KB)
// ---------------------------------------------------------------------------
extern __shared__ float smem[];

__global__ void __launch_bounds__(256, 1)
loss_kernel(const int* __restrict__ labels, float* __restrict__ out) {
    float* As = smem;                    // [k][row], pitch 132
    float* Bs = smem + 128 * PITCH;      // [k][col], pitch 132
    __shared__ int lrow[TM];
    __shared__ int lcolS[TN];
    __shared__ float wsum[8];

    const int b     = blockIdx.y;
    const int rbase = blockIdx.x * TM;
    const int tid   = threadIdx.x;
    const int tx    = tid & 15;
    const int ty    = tid >> 4;

    const float* vb = g_vt + (size_t)b * N_ * C_;
    const int*   lb = labels + b * N_;

    // Load A tile: rows [rbase, rbase+128), all K; store transposed As[k][r]
    for (int idx = tid; idx < TM * C_; idx += 256) {
        int r = idx >> 7, c = idx & 127;
        As[c * PITCH + r] = vb[(size_t)(rbase + r) * C_ + c];
    }
    if (tid < TM) lrow[tid] = lb[rbase + tid];
    __syncthreads();

    int   myrow[8], mylab[8];
    float post[8], tott[8];
    #pragma unroll
    for (int i = 0; i < 8; i++) {
        myrow[i] = rbase + ty * 8 + i;
        mylab[i] = lrow[ty * 8 + i];
        post[i] = 0.0f;
        tott[i] = 0.0f;
    }

    for (int ct = 0; ct < N_ / TN; ct++) {
        const int cbase = ct * TN;
        __syncthreads();   // all threads done reading previous Bs
        for (int idx = tid; idx < TN * C_; idx += 256) {
            int r = idx >> 7, c = idx & 127;
            Bs[c * PITCH + r] = vb[(size_t)(cbase + r) * C_ + c];
        }
        if (tid < TN) lcolS[tid] = lb[cbase + tid];
        __syncthreads();

        float acc[8][8];
        #pragma unroll
        for (int i = 0; i < 8; i++)
            #pragma unroll
            for (int j = 0; j < 8; j++) acc[i][j] = 0.0f;

        #pragma unroll 4
        for (int k = 0; k < C_; k++) {
            float4 a0 = *(const float4*)(As + k * PITCH + ty * 8);
            float4 a1 = *(const float4*)(As + k * PITCH + ty * 8 + 4);
            float4 b0 = *(const float4*)(Bs + k * PITCH + tx * 8);
            float4 b1 = *(const float4*)(Bs + k * PITCH + tx * 8 + 4);
            float av[8] = {a0.x, a0.y, a0.z, a0.w, a1.x, a1.y, a1.z, a1.w};
            float bv[8] = {b0.x, b0.y, b0.z, b0.w, b1.x, b1.y, b1.z, b1.w};
            #pragma unroll
            for (int i = 0; i < 8; i++)
                #pragma unroll
                for (int j = 0; j < 8; j++)
                    acc[i][j] = fmaf(av[i], bv[j], acc[i][j]);
        }

        // Fused epilogue: exp, diagonal removal, label masking
        int gcol[8], clab[8];
        #pragma unroll
        for (int j = 0; j < 8; j++) {
            gcol[j] = cbase + tx * 8 + j;
            clab[j] = lcolS[tx * 8 + j];
        }
        #pragma unroll
        for (int i = 0; i < 8; i++) {
            float p = 0.0f, t2 = 0.0f;
            #pragma unroll
            for (int j = 0; j < 8; j++) {
                float e = __expf(acc[i][j] * TINV);
                e = (myrow[i] == gcol[j]) ? 0.0f : e;   // remove diagonal
                t2 += e;
                p += (mylab[i] == clab[j]) ? e : 0.0f;  // positives
            }
            post[i] += p;
            tott[i] += t2;
        }
    }

    // Cross-thread reduction: each row's partials live in 16 tx-threads.
    __syncthreads();                    // done with As/Bs; reuse for reduction
    float* redp = smem;                 // [128][16]
    float* redt = smem + TM * 16;       // [128][16]
    #pragma unroll
    for (int i = 0; i < 8; i++) {
        redp[(ty * 8 + i) * 16 + tx] = post[i];
        redt[(ty * 8 + i) * 16 + tx] = tott[i];
    }
    __syncthreads();

    float dev = 0.0f;
    if (tid < TM) {
        float p = 0.0f, t2 = 0.0f;
        #pragma unroll
        for (int j = 0; j < 16; j++) {
            p  += redp[tid * 16 + j];
            t2 += redt[tid * 16 + j];
        }
        dev = __logf(t2) - __logf(p);   // -log(pos/(pos+neg))
    }

    // Block-reduce dev and accumulate scaled mean into out
    #pragma unroll
    for (int o = 16; o > 0; o >>= 1) dev += __shfl_xor_sync(0xffffffffu, dev, o);
    if ((tid & 31) == 0) wsum[tid >> 5] = dev;
    __syncthreads();
    if (tid == 0) {
        float s = 0.0f;
        #pragma unroll
        for (int w = 0; w < 8; w++) s += wsum[w];
        atomicAdd(out, s * (1.0f / ((float)B_ * (float)N_)));
    }
}

// ---------------------------------------------------------------------------
// Launch
// ---------------------------------------------------------------------------
extern "C" void kernel_launch(void* const* d_in, const int* in_sizes, int n_in,
                              void* d_out, int out_size) {
    const float* feat   = (const float*)d_in[0];
    const int*   labels = (const int*)d_in[1];
    float*       out    = (float*)d_out;

    zero_out_kernel<<<1, 1>>>(out);

    dim3 gn(N_ / 32, B_);
    normalize_kernel<<<gn, 256>>>(feat);

    const size_t smem_bytes = (size_t)2 * 128 * PITCH * sizeof(float); // 135168
    cudaFuncSetAttribute(loss_kernel,
                         cudaFuncAttributeMaxDynamicSharedMemorySize,
                         (int)smem_bytes);
    dim3 gl(N_ / TM, B_);
    loss_kernel<<<gl, 256, smem_bytes>>>(labels, out);
}

// round 5
// speedup vs baseline: 1.0036x; 1.0009x over previous
#include <cuda_runtime.h>
#include <math.h>

// Problem constants (fixed per reference setup_inputs)
#define B_   8
#define C_   128
#define N_   4096
#define TINV 10.0f        // 1/TEMP
#define EPSN 1e-12f

#define TM 128            // rows per block tile
#define TN 128            // cols per block tile
#define PITCH 132         // smem pitch (multiple of 4 for float4 alignment)

// Scratch: normalized features, [b][n][c] layout (16 MB)
__device__ float g_vt[(size_t)B_ * N_ * C_];

// ---------------------------------------------------------------------------
// Kernel 0: zero the output scalar (harness poisons d_out)
// ---------------------------------------------------------------------------
__global__ void zero_out_kernel(float* out) { out[0] = 0.0f; }

// ---------------------------------------------------------------------------
// Kernel 1: normalize + transpose.
// features [B][C][N] -> g_vt [B][N][C], each point L2-normalized over C.
// One block handles 32 points of one batch. 256 threads.
// ---------------------------------------------------------------------------
__global__ void normalize_kernel(const float* __restrict__ feat) {
    __shared__ float t[C_][33];     // padded to kill bank conflicts
    __shared__ float invn[32];
    const int b   = blockIdx.y;
    const int n0  = blockIdx.x * 32;
    const int tid = threadIdx.x;

    const float* fb = feat + (size_t)b * C_ * N_;

    // Load [C=128][32] tile, coalesced along n
    for (int idx = tid; idx < C_ * 32; idx += 256) {
        int c = idx >> 5, nl = idx & 31;
        t[c][nl] = fb[(size_t)c * N_ + n0 + nl];
    }
    __syncthreads();

    // Each of 8 warps computes norms for 4 points
    const int w = tid >> 5, lane = tid & 31;
    #pragma unroll
    for (int p = 0; p < 4; p++) {
        int nl = w * 4 + p;
        float v0 = t[lane     ][nl];
        float v1 = t[lane + 32][nl];
        float v2 = t[lane + 64][nl];
        float v3 = t[lane + 96][nl];
        float s = v0 * v0 + v1 * v1 + v2 * v2 + v3 * v3;
        #pragma unroll
        for (int o = 16; o > 0; o >>= 1) s += __shfl_xor_sync(0xffffffffu, s, o);
        if (lane == 0) invn[nl] = 1.0f / fmaxf(sqrtf(s), EPSN);
    }
    __syncthreads();

    // Write normalized, transposed: vt[b][n][c] (coalesced along c)
    float* vb = g_vt + ((size_t)b * N_ + n0) * C_;
    for (int idx = tid; idx < 32 * C_; idx += 256) {
        int nl = idx >> 7, c = idx & 127;
        vb[(size_t)nl * C_ + c] = t[c][nl] * invn[nl];
    }
}

// ---------------------------------------------------------------------------
// Kernel 2: fused S = exp(V.V^T * 10), masked row-reductions, log, and
// global mean accumulation. Block = 128 rows of one batch; loops over all
// 4096 columns in 128-wide tiles. 256 threads, 8x8 micro-tile each.
// Dynamic smem: As[128k][132] + Bs[128k][132]  (~132 KB)
// ---------------------------------------------------------------------------
extern __shared__ float smem[];

__global__ void __launch_bounds__(256, 1)
loss_kernel(const int* __restrict__ labels, float* __restrict__ out) {
    float* As = smem;                    // [k][row], pitch 132
    float* Bs = smem + 128 * PITCH;      // [k][col], pitch 132
    __shared__ int lrow[TM];
    __shared__ int lcolS[TN];
    __shared__ float wsum[8];

    const int b     = blockIdx.y;
    const int rbase = blockIdx.x * TM;
    const int tid   = threadIdx.x;
    const int tx    = tid & 15;
    const int ty    = tid >> 4;

    const float* vb = g_vt + (size_t)b * N_ * C_;
    const int*   lb = labels + b * N_;

    // Load A tile: rows [rbase, rbase+128), all K; store transposed As[k][r]
    for (int idx = tid; idx < TM * C_; idx += 256) {
        int r = idx >> 7, c = idx & 127;
        As[c * PITCH + r] = vb[(size_t)(rbase + r) * C_ + c];
    }
    if (tid < TM) lrow[tid] = lb[rbase + tid];
    __syncthreads();

    int   myrow[8], mylab[8];
    float post[8], tott[8];
    #pragma unroll
    for (int i = 0; i < 8; i++) {
        myrow[i] = rbase + ty * 8 + i;
        mylab[i] = lrow[ty * 8 + i];
        post[i] = 0.0f;
        tott[i] = 0.0f;
    }

    for (int ct = 0; ct < N_ / TN; ct++) {
        const int cbase = ct * TN;
        __syncthreads();   // all threads done reading previous Bs
        for (int idx = tid; idx < TN * C_; idx += 256) {
            int r = idx >> 7, c = idx & 127;
            Bs[c * PITCH + r] = vb[(size_t)(cbase + r) * C_ + c];
        }
        if (tid < TN) lcolS[tid] = lb[cbase + tid];
        __syncthreads();

        float acc[8][8];
        #pragma unroll
        for (int i = 0; i < 8; i++)
            #pragma unroll
            for (int j = 0; j < 8; j++) acc[i][j] = 0.0f;

        #pragma unroll 4
        for (int k = 0; k < C_; k++) {
            float4 a0 = *(const float4*)(As + k * PITCH + ty * 8);
            float4 a1 = *(const float4*)(As + k * PITCH + ty * 8 + 4);
            float4 b0 = *(const float4*)(Bs + k * PITCH + tx * 8);
            float4 b1 = *(const float4*)(Bs + k * PITCH + tx * 8 + 4);
            float av[8] = {a0.x, a0.y, a0.z, a0.w, a1.x, a1.y, a1.z, a1.w};
            float bv[8] = {b0.x, b0.y, b0.z, b0.w, b1.x, b1.y, b1.z, b1.w};
            #pragma unroll
            for (int i = 0; i < 8; i++)
                #pragma unroll
                for (int j = 0; j < 8; j++)
                    acc[i][j] = fmaf(av[i], bv[j], acc[i][j]);
        }

        // Fused epilogue: exp, diagonal removal, label masking
        int gcol[8], clab[8];
        #pragma unroll
        for (int j = 0; j < 8; j++) {
            gcol[j] = cbase + tx * 8 + j;
            clab[j] = lcolS[tx * 8 + j];
        }
        #pragma unroll
        for (int i = 0; i < 8; i++) {
            float p = 0.0f, t2 = 0.0f;
            #pragma unroll
            for (int j = 0; j < 8; j++) {
                float e = __expf(acc[i][j] * TINV);
                e = (myrow[i] == gcol[j]) ? 0.0f : e;   // remove diagonal
                t2 += e;
                p += (mylab[i] == clab[j]) ? e : 0.0f;  // positives
            }
            post[i] += p;
            tott[i] += t2;
        }
    }

    // Cross-thread reduction: each row's partials live in 16 tx-threads.
    __syncthreads();                    // done with As/Bs; reuse for reduction
    float* redp = smem;                 // [128][16]
    float* redt = smem + TM * 16;       // [128][16]
    #pragma unroll
    for (int i = 0; i < 8; i++) {
        redp[(ty * 8 + i) * 16 + tx] = post[i];
        redt[(ty * 8 + i) * 16 + tx] = tott[i];
    }
    __syncthreads();

    float dev = 0.0f;
    if (tid < TM) {
        float p = 0.0f, t2 = 0.0f;
        #pragma unroll
        for (int j = 0; j < 16; j++) {
            p  += redp[tid * 16 + j];
            t2 += redt[tid * 16 + j];
        }
        dev = __logf(t2) - __logf(p);   // -log(pos/(pos+neg))
    }

    // Block-reduce dev and accumulate scaled mean into out
    #pragma unroll
    for (int o = 16; o > 0; o >>= 1) dev += __shfl_xor_sync(0xffffffffu, dev, o);
    if ((tid & 31) == 0) wsum[tid >> 5] = dev;
    __syncthreads();
    if (tid == 0) {
        float s = 0.0f;
        #pragma unroll
        for (int w = 0; w < 8; w++) s += wsum[w];
        atomicAdd(out, s * (1.0f / ((float)B_ * (float)N_)));
    }
}

// ---------------------------------------------------------------------------
// Launch
// ---------------------------------------------------------------------------
extern "C" void kernel_launch(void* const* d_in, const int* in_sizes, int n_in,
                              void* d_out, int out_size) {
    const float* feat   = (const float*)d_in[0];
    const int*   labels = (const int*)d_in[1];
    float*       out    = (float*)d_out;

    zero_out_kernel<<<1, 1>>>(out);

    dim3 gn(N_ / 32, B_);
    normalize_kernel<<<gn, 256>>>(feat);

    const size_t smem_bytes = (size_t)2 * 128 * PITCH * sizeof(float); // 135168
    cudaFuncSetAttribute(loss_kernel,
                         cudaFuncAttributeMaxDynamicSharedMemorySize,
                         (int)smem_bytes);
    dim3 gl(N_ / TM, B_);
    loss_kernel<<<gl, 256, smem_bytes>>>(labels, out);
}